// round 1
// baseline (speedup 1.0000x reference)
#include <cuda_runtime.h>
#include <math.h>

#define BB 8
#define CC 64
#define C4 256
#define H2 128
#define W2 128

// Scratch (NHWC: [b][i][j][c4]) + transformed weights
__device__ float g_t0[(size_t)BB * H2 * W2 * C4];
__device__ float g_t1[(size_t)BB * H2 * W2 * C4];
__device__ float g_dwT[9 * C4];          // [tap][c]
__device__ float g_pwT[C4 * C4];         // [ic][oc]
__device__ float g_cvT[9 * C4 * C4];     // [tap][ic][oc]

__device__ __forceinline__ float gelu_exact(float v) {
    return 0.5f * v * (1.0f + erff(v * 0.70710678118654752f));
}

// ---------------------------------------------------------------------------
// Weight transforms (tiny; runs every launch, deterministic)
// ---------------------------------------------------------------------------
__global__ void prep_kernel(const float* __restrict__ dw_w,
                            const float* __restrict__ pw_w,
                            const float* __restrict__ cv_w) {
    int idx0 = blockIdx.x * blockDim.x + threadIdx.x;
    int stride = gridDim.x * blockDim.x;
    for (int idx = idx0; idx < 9 * C4; idx += stride) {
        int tap = idx >> 8, c = idx & 255;
        g_dwT[idx] = dw_w[c * 9 + tap];
    }
    for (int idx = idx0; idx < C4 * C4; idx += stride) {
        int ic = idx >> 8, oc = idx & 255;
        g_pwT[idx] = pw_w[oc * C4 + ic];
    }
    for (int idx = idx0; idx < 9 * C4 * C4; idx += stride) {
        int tap = idx >> 16;
        int r = idx & 65535;
        int ic = r >> 8, oc = r & 255;
        g_cvT[idx] = cv_w[(oc * C4 + ic) * 9 + tap];
    }
}

// ---------------------------------------------------------------------------
// DWT + transpose:  x (NCHW 8x64x256x256) -> t0 (NHWC [b][i][j][4c+k])
//   t0[b][i][j][4c+k] = subband_k[b][c][j][i], from x rows 2j..2j+1, cols 2i..2i+1
// ---------------------------------------------------------------------------
__global__ void dwt_kernel(const float* __restrict__ x) {
    __shared__ float4 s[16][17];
    int b = blockIdx.z;
    int j = blockIdx.y;
    int ctile = blockIdx.x >> 3;   // 0..3
    int itile = blockIdx.x & 7;    // 0..7
    int tx = threadIdx.x, ty = threadIdx.y;

    // phase 1: coalesced reads from x (tx over i)
    int c = ctile * 16 + ty;
    int i = itile * 16 + tx;
    const float* p = x + (((size_t)(b * CC + c) * 256) + 2 * j) * 256 + 2 * i;
    float2 top = *(const float2*)p;
    float2 bot = *(const float2*)(p + 256);
    float a = top.x, bq = top.y, cq = bot.x, d = bot.y;
    s[ty][tx] = make_float4((a + bq + cq + d) * 0.5f,
                            (a + bq - cq - d) * 0.5f,
                            (a - bq + cq - d) * 0.5f,
                            (a - bq - cq + d) * 0.5f);
    __syncthreads();

    // phase 2: coalesced writes to t0 (tx over c)
    float4 v = s[tx][ty];
    int c2 = ctile * 16 + tx;
    int i2 = itile * 16 + ty;
    *(float4*)(g_t0 + ((((size_t)b * H2 + i2) * W2) + j) * C4 + 4 * c2) = v;
}

// ---------------------------------------------------------------------------
// Depthwise 3x3 + bias:  t0 -> t1 (NHWC)
// ---------------------------------------------------------------------------
__global__ void dw_kernel(const float* __restrict__ dw_b) {
    int cq = threadIdx.x;                 // 0..63 (quad of channels)
    int j = blockIdx.x * 4 + threadIdx.y;
    int i = blockIdx.y;
    int b = blockIdx.z;
    int c0 = cq * 4;

    float4 acc = *(const float4*)(dw_b + c0);
    #pragma unroll
    for (int tap = 0; tap < 9; ++tap) {
        int ii = i + tap / 3 - 1;
        int jj = j + tap % 3 - 1;
        if ((unsigned)ii < (unsigned)H2 && (unsigned)jj < (unsigned)W2) {
            float4 v = *(const float4*)(g_t0 + ((((size_t)b * H2 + ii) * W2) + jj) * C4 + c0);
            float4 w = *(const float4*)(g_dwT + tap * C4 + c0);
            acc.x += v.x * w.x; acc.y += v.y * w.y;
            acc.z += v.z * w.z; acc.w += v.w * w.w;
        }
    }
    *(float4*)(g_t1 + ((((size_t)b * H2 + i) * W2) + j) * C4 + c0) = acc;
}

// ---------------------------------------------------------------------------
// Implicit-GEMM conv: 128(M=j) x 128(N=oc) tile, K = TAPS*256, 8x8 per thread.
//   TAPS==1: pointwise (t1 -> t0), bias only.
//   TAPS==9: dense 3x3 (t0 -> t1), bias + exact GELU.
// ---------------------------------------------------------------------------
template<int TAPS, bool DO_GELU>
__global__ void __launch_bounds__(256, 2)
conv_gemm_kernel(const float* __restrict__ bias) {
    const float* __restrict__ in  = (TAPS == 9) ? g_t0 : g_t1;
    const float* __restrict__ wT  = (TAPS == 9) ? g_cvT : g_pwT;
    float* __restrict__ outp      = (TAPS == 9) ? g_t1 : g_t0;

    __shared__ float As[8][132];
    __shared__ float Bs[8][128];

    int bi = blockIdx.x;
    int b = bi >> 7;
    int i = bi & 127;
    int oc0 = blockIdx.y * 128;
    int t = threadIdx.x;
    int tx = t & 15, ty = t >> 4;

    int mload = t & 127;          // A-load: m index (j)
    int kq = (t >> 7) * 4;        // A-load: kk base (4 consecutive ic via float4)
    int nload = (t & 31) * 4;     // B-load: n base
    int kb = t >> 5;              // B-load: kk

    float acc[8][8];
    #pragma unroll
    for (int m = 0; m < 8; m++)
        #pragma unroll
        for (int n = 0; n < 8; n++) acc[m][n] = 0.0f;

    const int KT = TAPS * 32;

    const float* row_base = in + (size_t)b * H2 * W2 * C4;

    float4 av, bv;
    {   // prefetch kt = 0 (tap 0)
        if (TAPS == 9) {
            int ii = i - 1, jj = mload - 1;
            bool ok = (unsigned)ii < (unsigned)H2 && (unsigned)jj < (unsigned)W2;
            av = ok ? *(const float4*)(row_base + ((size_t)ii * W2 + jj) * C4 + kq)
                    : make_float4(0.f, 0.f, 0.f, 0.f);
        } else {
            av = *(const float4*)(row_base + ((size_t)i * W2 + mload) * C4 + kq);
        }
        bv = *(const float4*)(wT + (size_t)kb * C4 + oc0 + nload);
    }

    for (int kt = 0; kt < KT; ++kt) {
        As[kq + 0][mload] = av.x;
        As[kq + 1][mload] = av.y;
        As[kq + 2][mload] = av.z;
        As[kq + 3][mload] = av.w;
        *(float4*)&Bs[kb][nload] = bv;
        __syncthreads();

        if (kt + 1 < KT) {   // prefetch next tile into registers
            int kn = kt + 1;
            int tap = (TAPS == 9) ? (kn >> 5) : 0;
            int ic0 = (kn & 31) * 8;
            if (TAPS == 9) {
                int di = tap / 3 - 1, dj = tap % 3 - 1;
                int ii = i + di, jj = mload + dj;
                bool ok = (unsigned)ii < (unsigned)H2 && (unsigned)jj < (unsigned)W2;
                av = ok ? *(const float4*)(row_base + ((size_t)ii * W2 + jj) * C4 + ic0 + kq)
                        : make_float4(0.f, 0.f, 0.f, 0.f);
            } else {
                av = *(const float4*)(row_base + ((size_t)i * W2 + mload) * C4 + ic0 + kq);
            }
            bv = *(const float4*)(wT + ((size_t)tap * C4 + ic0 + kb) * C4 + oc0 + nload);
        }

        #pragma unroll
        for (int kk = 0; kk < 8; ++kk) {
            float4 a0 = *(const float4*)&As[kk][tx * 8];
            float4 a1 = *(const float4*)&As[kk][tx * 8 + 4];
            float4 b0 = *(const float4*)&Bs[kk][ty * 8];
            float4 b1 = *(const float4*)&Bs[kk][ty * 8 + 4];
            float am[8] = {a0.x, a0.y, a0.z, a0.w, a1.x, a1.y, a1.z, a1.w};
            float bn[8] = {b0.x, b0.y, b0.z, b0.w, b1.x, b1.y, b1.z, b1.w};
            #pragma unroll
            for (int m = 0; m < 8; m++)
                #pragma unroll
                for (int n = 0; n < 8; n++)
                    acc[m][n] += am[m] * bn[n];
        }
        __syncthreads();
    }

    // epilogue: bias (+GELU), vectorized stores
    float bz[8];
    #pragma unroll
    for (int n = 0; n < 8; n++) bz[n] = bias[oc0 + ty * 8 + n];

    #pragma unroll
    for (int m = 0; m < 8; m++) {
        int j = tx * 8 + m;
        float* op = outp + ((((size_t)b * H2 + i) * W2) + j) * C4 + oc0 + ty * 8;
        float r[8];
        #pragma unroll
        for (int n = 0; n < 8; n++) {
            float v = acc[m][n] + bz[n];
            r[n] = DO_GELU ? gelu_exact(v) : v;
        }
        *(float4*)(op)     = make_float4(r[0], r[1], r[2], r[3]);
        *(float4*)(op + 4) = make_float4(r[4], r[5], r[6], r[7]);
    }
}

// ---------------------------------------------------------------------------
// Inverse transpose + IDWT:  t1 (NHWC) -> out (NCHW 8x64x256x256)
//   ll2[b][c][h2][w2] = t1[b][w2][h2][4c+k]; out[b][c][2h2+r][2w2+s]
// ---------------------------------------------------------------------------
__global__ void idwt_kernel(float* __restrict__ out) {
    __shared__ float4 s[16][17];
    int b = blockIdx.z;
    int h2 = blockIdx.y;
    int ctile = blockIdx.x >> 3;
    int wtile = blockIdx.x & 7;
    int tx = threadIdx.x, ty = threadIdx.y;

    // phase 1: coalesced reads (tx over c)
    int c = ctile * 16 + tx;
    int w2 = wtile * 16 + ty;
    s[ty][tx] = *(const float4*)(g_t1 + ((((size_t)b * H2 + w2) * W2) + h2) * C4 + 4 * c);
    __syncthreads();

    // phase 2: coalesced writes (tx over w2)
    float4 v = s[tx][ty];
    int c2 = ctile * 16 + ty;
    int w2b = wtile * 16 + tx;
    float ll = v.x, ch = v.y, cv = v.z, cd = v.w;
    float a  = (ll + ch + cv + cd) * 0.5f;
    float bq = (ll + ch - cv - cd) * 0.5f;
    float cq = (ll - ch + cv - cd) * 0.5f;
    float dq = (ll - ch - cv + cd) * 0.5f;
    float* o = out + (((size_t)(b * CC + c2) * 256) + 2 * h2) * 256 + 2 * w2b;
    *(float2*)o         = make_float2(a, bq);
    *(float2*)(o + 256) = make_float2(cq, dq);
}

// ---------------------------------------------------------------------------
extern "C" void kernel_launch(void* const* d_in, const int* in_sizes, int n_in,
                              void* d_out, int out_size) {
    const float* x    = (const float*)d_in[0];
    const float* dw_w = (const float*)d_in[1];
    const float* dw_b = (const float*)d_in[2];
    const float* pw_w = (const float*)d_in[3];
    const float* pw_b = (const float*)d_in[4];
    const float* cv_w = (const float*)d_in[5];
    const float* cv_b = (const float*)d_in[6];
    float* out = (float*)d_out;

    prep_kernel<<<1024, 256>>>(dw_w, pw_w, cv_w);

    dwt_kernel<<<dim3(32, 128, BB), dim3(16, 16)>>>(x);

    dw_kernel<<<dim3(32, 128, BB), dim3(64, 4)>>>(dw_b);

    // pointwise 1x1: t1 -> t0
    conv_gemm_kernel<1, false><<<dim3(1024, 2), 256>>>(pw_b);

    // dense 3x3 + GELU: t0 -> t1
    conv_gemm_kernel<9, true><<<dim3(1024, 2), 256>>>(cv_b);

    idwt_kernel<<<dim3(32, 128, BB), dim3(16, 16)>>>(out);
}

// round 3
// speedup vs baseline: 2.5223x; 2.5223x over previous
#include <cuda_runtime.h>
#include <cuda_bf16.h>
#include <math.h>
#include <stdint.h>

#define BB 8
#define CC 64
#define C4 256
#define H2 128
#define W2 128

typedef __nv_bfloat16 bf16;

// ---------------------------------------------------------------------------
// Global scratch
// ---------------------------------------------------------------------------
__device__ float g_t0[(size_t)BB * H2 * W2 * C4];     // fp32 NHWC scratch
__device__ bf16 g_a_hi[(size_t)BB * H2 * W2 * C4];    // dw output split
__device__ bf16 g_a_lo[(size_t)BB * H2 * W2 * C4];
__device__ bf16 g_b_hi[(size_t)BB * H2 * W2 * C4];    // pw output split
__device__ bf16 g_b_lo[(size_t)BB * H2 * W2 * C4];
__device__ float g_dwT[9 * C4];                        // [tap][c]
__device__ bf16 g_pw_hi[C4 * C4];                      // [oc][ic]
__device__ bf16 g_pw_lo[C4 * C4];
__device__ bf16 g_cv_hi[(size_t)C4 * 9 * C4];          // [oc][tap*256+ic]
__device__ bf16 g_cv_lo[(size_t)C4 * 9 * C4];

__device__ __forceinline__ float gelu_exact(float v) {
    return 0.5f * v * (1.0f + erff(v * 0.70710678118654752f));
}

__device__ __forceinline__ uint32_t smem_to_u32(const void* p) {
    uint32_t a;
    asm("{ .reg .u64 t; cvta.to.shared.u64 t, %1; cvt.u32.u64 %0, t; }" : "=r"(a) : "l"(p));
    return a;
}

// cp.async 16B with zero-fill predicate
__device__ __forceinline__ void cpa16(uint32_t dst, const void* src, bool ok) {
    int sz = ok ? 16 : 0;
    asm volatile("cp.async.cg.shared.global [%0], [%1], 16, %2;\n"
                 :: "r"(dst), "l"(src), "r"(sz));
}
__device__ __forceinline__ void cpa_commit() {
    asm volatile("cp.async.commit_group;\n" ::: "memory");
}
template<int N>
__device__ __forceinline__ void cpa_wait() {
    asm volatile("cp.async.wait_group %0;\n" :: "n"(N) : "memory");
}

__device__ __forceinline__ void ldsm4(uint32_t* r, uint32_t addr) {
    asm volatile("ldmatrix.sync.aligned.m8n8.x4.shared.b16 {%0,%1,%2,%3}, [%4];"
                 : "=r"(r[0]), "=r"(r[1]), "=r"(r[2]), "=r"(r[3]) : "r"(addr));
}

__device__ __forceinline__ void mma16816(float* c, const uint32_t* a,
                                         uint32_t b0, uint32_t b1) {
    asm volatile(
        "mma.sync.aligned.m16n8k16.row.col.f32.bf16.bf16.f32 "
        "{%0,%1,%2,%3}, {%4,%5,%6,%7}, {%8,%9}, {%0,%1,%2,%3};"
        : "+f"(c[0]), "+f"(c[1]), "+f"(c[2]), "+f"(c[3])
        : "r"(a[0]), "r"(a[1]), "r"(a[2]), "r"(a[3]), "r"(b0), "r"(b1));
}

// SMEM: per stage [Ah|Al|Bh|Bl], each 128 rows x 80B (32 bf16 data + pad)
#define ROWP 80
#define TILE_B (128 * ROWP)         // 10240
#define STAGE_B (4 * TILE_B)        // 40960
#define SMEM_DYN (2 * STAGE_B)      // 81920

// ---------------------------------------------------------------------------
// Weight transforms
// ---------------------------------------------------------------------------
__global__ void prep_kernel(const float* __restrict__ dw_w,
                            const float* __restrict__ pw_w,
                            const float* __restrict__ cv_w) {
    int idx0 = blockIdx.x * blockDim.x + threadIdx.x;
    int stride = gridDim.x * blockDim.x;
    for (int idx = idx0; idx < 9 * C4; idx += stride) {
        int tap = idx >> 8, c = idx & 255;
        g_dwT[idx] = dw_w[c * 9 + tap];
    }
    for (int idx = idx0; idx < C4 * C4; idx += stride) {
        float v = pw_w[idx];                       // already [oc][ic]
        bf16 h = __float2bfloat16(v);
        g_pw_hi[idx] = h;
        g_pw_lo[idx] = __float2bfloat16(v - __bfloat162float(h));
    }
    for (int idx = idx0; idx < C4 * 9 * C4; idx += stride) {
        int oc = idx / (9 * C4);
        int r = idx % (9 * C4);
        int tap = r >> 8, ic = r & 255;
        float v = cv_w[((size_t)oc * C4 + ic) * 9 + tap];
        bf16 h = __float2bfloat16(v);
        g_cv_hi[idx] = h;
        g_cv_lo[idx] = __float2bfloat16(v - __bfloat162float(h));
    }
}

// ---------------------------------------------------------------------------
// DWT + transpose:  x (NCHW) -> t0 (fp32 NHWC [b][i][j][4c+k])
// ---------------------------------------------------------------------------
__global__ void dwt_kernel(const float* __restrict__ x) {
    __shared__ float4 s[16][17];
    int b = blockIdx.z;
    int j = blockIdx.y;
    int ctile = blockIdx.x >> 3;
    int itile = blockIdx.x & 7;
    int tx = threadIdx.x, ty = threadIdx.y;

    int c = ctile * 16 + ty;
    int i = itile * 16 + tx;
    const float* p = x + (((size_t)(b * CC + c) * 256) + 2 * j) * 256 + 2 * i;
    float2 top = *(const float2*)p;
    float2 bot = *(const float2*)(p + 256);
    float a = top.x, bq = top.y, cq = bot.x, d = bot.y;
    s[ty][tx] = make_float4((a + bq + cq + d) * 0.5f,
                            (a + bq - cq - d) * 0.5f,
                            (a - bq + cq - d) * 0.5f,
                            (a - bq - cq + d) * 0.5f);
    __syncthreads();

    float4 v = s[tx][ty];
    int c2 = ctile * 16 + tx;
    int i2 = itile * 16 + ty;
    *(float4*)(g_t0 + ((((size_t)b * H2 + i2) * W2) + j) * C4 + 4 * c2) = v;
}

// ---------------------------------------------------------------------------
// Depthwise 3x3 + bias (fp32), output split to bf16 hi/lo
// ---------------------------------------------------------------------------
__global__ void dw_kernel(const float* __restrict__ dw_b) {
    int cq = threadIdx.x;
    int j = blockIdx.x * 4 + threadIdx.y;
    int i = blockIdx.y;
    int b = blockIdx.z;
    int c0 = cq * 4;

    float4 acc = *(const float4*)(dw_b + c0);
    #pragma unroll
    for (int tap = 0; tap < 9; ++tap) {
        int ii = i + tap / 3 - 1;
        int jj = j + tap % 3 - 1;
        if ((unsigned)ii < (unsigned)H2 && (unsigned)jj < (unsigned)W2) {
            float4 v = *(const float4*)(g_t0 + ((((size_t)b * H2 + ii) * W2) + jj) * C4 + c0);
            float4 w = *(const float4*)(g_dwT + tap * C4 + c0);
            acc.x += v.x * w.x; acc.y += v.y * w.y;
            acc.z += v.z * w.z; acc.w += v.w * w.w;
        }
    }
    size_t o = ((((size_t)b * H2 + i) * W2) + j) * C4 + c0;
    float vv[4] = {acc.x, acc.y, acc.z, acc.w};
    bf16 hb[4], lb[4];
    #pragma unroll
    for (int q = 0; q < 4; q++) {
        hb[q] = __float2bfloat16(vv[q]);
        lb[q] = __float2bfloat16(vv[q] - __bfloat162float(hb[q]));
    }
    *(uint2*)(g_a_hi + o) = *(uint2*)hb;
    *(uint2*)(g_a_lo + o) = *(uint2*)lb;
}

// ---------------------------------------------------------------------------
// mma.sync GEMM conv. CTA: M=128(j) x N=128(oc), K-chunk 32, 2-stage cp.async.
// bf16 2-term split: acc += Ah*Bh + Ah*Bl + Al*Bh.
// TAPS==1: pw, a_* -> b_* (bias, bf16 re-split). TAPS==9: cv, b_* -> g_t0 (bias+GELU).
// ---------------------------------------------------------------------------
template<int TAPS>
__device__ __forceinline__ void load_stage(uint32_t sb, int stage,
                                           const bf16* __restrict__ ah,
                                           const bf16* __restrict__ al,
                                           const bf16* __restrict__ wh,
                                           const bf16* __restrict__ wl,
                                           int b, int i, int oc0, int chunk, int t) {
    const int tap = (TAPS == 9) ? (chunk >> 3) : 0;
    const int ic0 = (TAPS == 9) ? ((chunk & 7) * 32) : (chunk * 32);
    const int KTOT = TAPS * 256;
    uint32_t st = sb + stage * STAGE_B;

    #pragma unroll
    for (int rep = 0; rep < 2; rep++) {
        int slot = t + rep * 256;      // 0..511
        int row = slot >> 2, q = slot & 3;
        int ii = (TAPS == 9) ? (i + tap / 3 - 1) : i;
        int jj = (TAPS == 9) ? (row + tap % 3 - 1) : row;
        bool ok = ((unsigned)ii < (unsigned)H2) && ((unsigned)jj < (unsigned)W2);
        if (!ok) { ii = 0; jj = 0; }
        size_t goff = (((size_t)b * H2 + ii) * W2 + jj) * (size_t)C4 + ic0 + q * 8;
        uint32_t dA = st + row * ROWP + q * 16;
        cpa16(dA, ah + goff, ok);
        cpa16(dA + TILE_B, al + goff, ok);
    }
    #pragma unroll
    for (int rep = 0; rep < 2; rep++) {
        int slot = t + rep * 256;
        int row = slot >> 2, q = slot & 3;
        size_t w = (size_t)(oc0 + row) * KTOT + tap * 256 + ic0 + q * 8;
        uint32_t dB = st + 2 * TILE_B + row * ROWP + q * 16;
        cpa16(dB, wh + w, true);
        cpa16(dB + TILE_B, wl + w, true);
    }
}

template<int TAPS, bool GELU_OUT>
__global__ void __launch_bounds__(256, 2)
gemm_mma_kernel(const float* __restrict__ bias) {
    extern __shared__ char smem[];
    uint32_t sb = smem_to_u32(smem);
    const int t = threadIdx.x;
    const int lane = t & 31, wid = t >> 5;
    const int mw = wid & 3, nw = wid >> 2;   // warp grid 4(m) x 2(n)
    const int oc0 = blockIdx.x * 128;
    const int bi = blockIdx.y;
    const int b = bi >> 7, i = bi & 127;

    const bf16* ah = (TAPS == 9) ? g_b_hi : g_a_hi;
    const bf16* al = (TAPS == 9) ? g_b_lo : g_a_lo;
    const bf16* wh = (TAPS == 9) ? g_cv_hi : g_pw_hi;
    const bf16* wl = (TAPS == 9) ? g_cv_lo : g_pw_lo;

    float acc[2][8][4];
    #pragma unroll
    for (int tm = 0; tm < 2; tm++)
        #pragma unroll
        for (int tn = 0; tn < 8; tn++)
            #pragma unroll
            for (int q = 0; q < 4; q++) acc[tm][tn][q] = 0.0f;

    // per-thread ldmatrix offsets (byte offsets within a tile)
    uint32_t aoff[2], boff[4];
    #pragma unroll
    for (int tm = 0; tm < 2; tm++)
        aoff[tm] = (mw * 32 + tm * 16 + (lane & 15)) * ROWP + (lane >> 4) * 16;
    #pragma unroll
    for (int g = 0; g < 4; g++)
        boff[g] = (nw * 64 + g * 16 + ((lane >> 4) & 1) * 8 + (lane & 7)) * ROWP
                + ((lane >> 3) & 1) * 16;

    const int NC = TAPS * 8;

    load_stage<TAPS>(sb, 0, ah, al, wh, wl, b, i, oc0, 0, t);
    cpa_commit();

    for (int c = 0; c < NC; c++) {
        if (c + 1 < NC) {
            load_stage<TAPS>(sb, (c + 1) & 1, ah, al, wh, wl, b, i, oc0, c + 1, t);
            cpa_commit();
            cpa_wait<1>();
        } else {
            cpa_wait<0>();
        }
        __syncthreads();

        uint32_t st = sb + (c & 1) * STAGE_B;
        uint32_t Ahp = st, Alp = st + TILE_B, Bhp = st + 2 * TILE_B, Blp = st + 3 * TILE_B;

        #pragma unroll
        for (int kh = 0; kh < 2; kh++) {
            uint32_t a[2][4], bh[4][4], bl[4][4];
            #pragma unroll
            for (int tm = 0; tm < 2; tm++) ldsm4(a[tm], Ahp + aoff[tm] + kh * 32);
            #pragma unroll
            for (int g = 0; g < 4; g++) ldsm4(bh[g], Bhp + boff[g] + kh * 32);
            // Ah * Bh
            #pragma unroll
            for (int tm = 0; tm < 2; tm++)
                #pragma unroll
                for (int g = 0; g < 4; g++) {
                    mma16816(acc[tm][2 * g],     a[tm], bh[g][0], bh[g][1]);
                    mma16816(acc[tm][2 * g + 1], a[tm], bh[g][2], bh[g][3]);
                }
            // Ah * Bl
            #pragma unroll
            for (int g = 0; g < 4; g++) ldsm4(bl[g], Blp + boff[g] + kh * 32);
            #pragma unroll
            for (int tm = 0; tm < 2; tm++)
                #pragma unroll
                for (int g = 0; g < 4; g++) {
                    mma16816(acc[tm][2 * g],     a[tm], bl[g][0], bl[g][1]);
                    mma16816(acc[tm][2 * g + 1], a[tm], bl[g][2], bl[g][3]);
                }
            // Al * Bh
            #pragma unroll
            for (int tm = 0; tm < 2; tm++) ldsm4(a[tm], Alp + aoff[tm] + kh * 32);
            #pragma unroll
            for (int tm = 0; tm < 2; tm++)
                #pragma unroll
                for (int g = 0; g < 4; g++) {
                    mma16816(acc[tm][2 * g],     a[tm], bh[g][0], bh[g][1]);
                    mma16816(acc[tm][2 * g + 1], a[tm], bh[g][2], bh[g][3]);
                }
        }
        __syncthreads();
    }

    // Epilogue from register accumulators
    const int r = lane >> 2, cpair = (lane & 3) * 2;
    #pragma unroll
    for (int tm = 0; tm < 2; tm++) {
        #pragma unroll
        for (int tn = 0; tn < 8; tn++) {
            int oc = oc0 + nw * 64 + tn * 8 + cpair;
            float bz0 = __ldg(bias + oc), bz1 = __ldg(bias + oc + 1);
            int j0 = mw * 32 + tm * 16 + r;
            #pragma unroll
            for (int half = 0; half < 2; half++) {
                int j = j0 + half * 8;
                float v0 = acc[tm][tn][half * 2 + 0] + bz0;
                float v1 = acc[tm][tn][half * 2 + 1] + bz1;
                size_t off = ((((size_t)b * H2 + i) * W2) + j) * C4 + oc;
                if (GELU_OUT) {
                    *(float2*)(g_t0 + off) = make_float2(gelu_exact(v0), gelu_exact(v1));
                } else {
                    bf16 h0 = __float2bfloat16(v0);
                    bf16 h1 = __float2bfloat16(v1);
                    bf16 l0 = __float2bfloat16(v0 - __bfloat162float(h0));
                    bf16 l1 = __float2bfloat16(v1 - __bfloat162float(h1));
                    bf16 hp[2] = {h0, h1};
                    bf16 lp[2] = {l0, l1};
                    *(uint32_t*)(g_b_hi + off) = *(uint32_t*)hp;
                    *(uint32_t*)(g_b_lo + off) = *(uint32_t*)lp;
                }
            }
        }
    }
}

// ---------------------------------------------------------------------------
// IDWT: t0 (fp32 NHWC) -> out (NCHW)
// ---------------------------------------------------------------------------
__global__ void idwt_kernel(float* __restrict__ out) {
    __shared__ float4 s[16][17];
    int b = blockIdx.z;
    int h2 = blockIdx.y;
    int ctile = blockIdx.x >> 3;
    int wtile = blockIdx.x & 7;
    int tx = threadIdx.x, ty = threadIdx.y;

    int c = ctile * 16 + tx;
    int w2 = wtile * 16 + ty;
    s[ty][tx] = *(const float4*)(g_t0 + ((((size_t)b * H2 + w2) * W2) + h2) * C4 + 4 * c);
    __syncthreads();

    float4 v = s[tx][ty];
    int c2 = ctile * 16 + ty;
    int w2b = wtile * 16 + tx;
    float ll = v.x, ch = v.y, cv = v.z, cd = v.w;
    float a  = (ll + ch + cv + cd) * 0.5f;
    float bq = (ll + ch - cv - cd) * 0.5f;
    float cq = (ll - ch + cv - cd) * 0.5f;
    float dq = (ll - ch - cv + cd) * 0.5f;
    float* o = out + (((size_t)(b * CC + c2) * 256) + 2 * h2) * 256 + 2 * w2b;
    *(float2*)o         = make_float2(a, bq);
    *(float2*)(o + 256) = make_float2(cq, dq);
}

// ---------------------------------------------------------------------------
extern "C" void kernel_launch(void* const* d_in, const int* in_sizes, int n_in,
                              void* d_out, int out_size) {
    const float* x    = (const float*)d_in[0];
    const float* dw_w = (const float*)d_in[1];
    const float* dw_b = (const float*)d_in[2];
    const float* pw_w = (const float*)d_in[3];
    const float* pw_b = (const float*)d_in[4];
    const float* cv_w = (const float*)d_in[5];
    const float* cv_b = (const float*)d_in[6];
    float* out = (float*)d_out;

    cudaFuncSetAttribute(gemm_mma_kernel<1, false>,
                         cudaFuncAttributeMaxDynamicSharedMemorySize, SMEM_DYN);
    cudaFuncSetAttribute(gemm_mma_kernel<9, true>,
                         cudaFuncAttributeMaxDynamicSharedMemorySize, SMEM_DYN);

    prep_kernel<<<512, 256>>>(dw_w, pw_w, cv_w);
    dwt_kernel<<<dim3(32, 128, BB), dim3(16, 16)>>>(x);
    dw_kernel<<<dim3(32, 128, BB), dim3(64, 4)>>>(dw_b);
    gemm_mma_kernel<1, false><<<dim3(2, 1024), 256, SMEM_DYN>>>(pw_b);
    gemm_mma_kernel<9, true><<<dim3(2, 1024), 256, SMEM_DYN>>>(cv_b);
    idwt_kernel<<<dim3(32, 128, BB), dim3(16, 16)>>>(out);
}

// round 4
// speedup vs baseline: 2.6631x; 1.0558x over previous
#include <cuda_runtime.h>
#include <cuda_bf16.h>
#include <math.h>
#include <stdint.h>

#define BB 8
#define CC 64
#define C4 256
#define H2 128
#define W2 128

typedef __nv_bfloat16 bf16;

// ---------------------------------------------------------------------------
// Global scratch
// ---------------------------------------------------------------------------
__device__ float g_t0[(size_t)BB * H2 * W2 * C4];     // fp32 NHWC scratch
__device__ bf16 g_a_hi[(size_t)BB * H2 * W2 * C4];    // dw output split
__device__ bf16 g_a_lo[(size_t)BB * H2 * W2 * C4];
__device__ bf16 g_b_hi[(size_t)BB * H2 * W2 * C4];    // pw output split
__device__ bf16 g_b_lo[(size_t)BB * H2 * W2 * C4];
__device__ float g_dwT[9 * C4];                        // [tap][c]
__device__ bf16 g_pw_hi[C4 * C4];                      // [oc][ic]
__device__ bf16 g_pw_lo[C4 * C4];
__device__ bf16 g_cv_hi[(size_t)C4 * 9 * C4];          // [oc][tap*256+ic]
__device__ bf16 g_cv_lo[(size_t)C4 * 9 * C4];

__device__ __forceinline__ float gelu_exact(float v) {
    return 0.5f * v * (1.0f + erff(v * 0.70710678118654752f));
}

__device__ __forceinline__ uint32_t smem_to_u32(const void* p) {
    uint32_t a;
    asm("{ .reg .u64 t; cvta.to.shared.u64 t, %1; cvt.u32.u64 %0, t; }" : "=r"(a) : "l"(p));
    return a;
}

__device__ __forceinline__ void cpa16(uint32_t dst, const void* src, bool ok) {
    int sz = ok ? 16 : 0;
    asm volatile("cp.async.cg.shared.global [%0], [%1], 16, %2;\n"
                 :: "r"(dst), "l"(src), "r"(sz));
}
__device__ __forceinline__ void cpa_commit() {
    asm volatile("cp.async.commit_group;\n" ::: "memory");
}
template<int N>
__device__ __forceinline__ void cpa_wait() {
    asm volatile("cp.async.wait_group %0;\n" :: "n"(N) : "memory");
}

__device__ __forceinline__ void ldsm4(uint32_t* r, uint32_t addr) {
    asm volatile("ldmatrix.sync.aligned.m8n8.x4.shared.b16 {%0,%1,%2,%3}, [%4];"
                 : "=r"(r[0]), "=r"(r[1]), "=r"(r[2]), "=r"(r[3]) : "r"(addr));
}

__device__ __forceinline__ void mma16816(float* c, const uint32_t* a,
                                         uint32_t b0, uint32_t b1) {
    asm volatile(
        "mma.sync.aligned.m16n8k16.row.col.f32.bf16.bf16.f32 "
        "{%0,%1,%2,%3}, {%4,%5,%6,%7}, {%8,%9}, {%0,%1,%2,%3};"
        : "+f"(c[0]), "+f"(c[1]), "+f"(c[2]), "+f"(c[3])
        : "r"(a[0]), "r"(a[1]), "r"(a[2]), "r"(a[3]), "r"(b0), "r"(b1));
}

// SMEM per stage: Ah(128x80) Al(128x80) Bh(256x80) Bl(256x80) = 61440B, 3 stages
#define ROWP 80
#define A_T (128 * ROWP)            // 10240
#define B_T (256 * ROWP)            // 20480
#define STAGE_B (2 * A_T + 2 * B_T) // 61440
#define OFF_AH 0
#define OFF_AL A_T
#define OFF_BH (2 * A_T)
#define OFF_BL (2 * A_T + B_T)
#define NSTAGE 3
#define SMEM_DYN (NSTAGE * STAGE_B) // 184320

// ---------------------------------------------------------------------------
// Weight transforms
// ---------------------------------------------------------------------------
__global__ void prep_kernel(const float* __restrict__ dw_w,
                            const float* __restrict__ pw_w,
                            const float* __restrict__ cv_w) {
    int idx0 = blockIdx.x * blockDim.x + threadIdx.x;
    int stride = gridDim.x * blockDim.x;
    for (int idx = idx0; idx < 9 * C4; idx += stride) {
        int tap = idx >> 8, c = idx & 255;
        g_dwT[idx] = dw_w[c * 9 + tap];
    }
    for (int idx = idx0; idx < C4 * C4; idx += stride) {
        float v = pw_w[idx];
        bf16 h = __float2bfloat16(v);
        g_pw_hi[idx] = h;
        g_pw_lo[idx] = __float2bfloat16(v - __bfloat162float(h));
    }
    for (int idx = idx0; idx < C4 * 9 * C4; idx += stride) {
        int oc = idx / (9 * C4);
        int r = idx % (9 * C4);
        int tap = r >> 8, ic = r & 255;
        float v = cv_w[((size_t)oc * C4 + ic) * 9 + tap];
        bf16 h = __float2bfloat16(v);
        g_cv_hi[idx] = h;
        g_cv_lo[idx] = __float2bfloat16(v - __bfloat162float(h));
    }
}

// ---------------------------------------------------------------------------
// DWT + transpose:  x (NCHW) -> t0 (fp32 NHWC [b][i][j][4c+k])
// ---------------------------------------------------------------------------
__global__ void dwt_kernel(const float* __restrict__ x) {
    __shared__ float4 s[16][17];
    int b = blockIdx.z;
    int j = blockIdx.y;
    int ctile = blockIdx.x >> 3;
    int itile = blockIdx.x & 7;
    int tx = threadIdx.x, ty = threadIdx.y;

    int c = ctile * 16 + ty;
    int i = itile * 16 + tx;
    const float* p = x + (((size_t)(b * CC + c) * 256) + 2 * j) * 256 + 2 * i;
    float2 top = *(const float2*)p;
    float2 bot = *(const float2*)(p + 256);
    float a = top.x, bq = top.y, cq = bot.x, d = bot.y;
    s[ty][tx] = make_float4((a + bq + cq + d) * 0.5f,
                            (a + bq - cq - d) * 0.5f,
                            (a - bq + cq - d) * 0.5f,
                            (a - bq - cq + d) * 0.5f);
    __syncthreads();

    float4 v = s[tx][ty];
    int c2 = ctile * 16 + tx;
    int i2 = itile * 16 + ty;
    *(float4*)(g_t0 + ((((size_t)b * H2 + i2) * W2) + j) * C4 + 4 * c2) = v;
}

// ---------------------------------------------------------------------------
// Depthwise 3x3 + bias (fp32), output split to bf16 hi/lo
// ---------------------------------------------------------------------------
__global__ void dw_kernel(const float* __restrict__ dw_b) {
    int cq = threadIdx.x;
    int j = blockIdx.x * 4 + threadIdx.y;
    int i = blockIdx.y;
    int b = blockIdx.z;
    int c0 = cq * 4;

    float4 acc = *(const float4*)(dw_b + c0);
    #pragma unroll
    for (int tap = 0; tap < 9; ++tap) {
        int ii = i + tap / 3 - 1;
        int jj = j + tap % 3 - 1;
        if ((unsigned)ii < (unsigned)H2 && (unsigned)jj < (unsigned)W2) {
            float4 v = *(const float4*)(g_t0 + ((((size_t)b * H2 + ii) * W2) + jj) * C4 + c0);
            float4 w = *(const float4*)(g_dwT + tap * C4 + c0);
            acc.x += v.x * w.x; acc.y += v.y * w.y;
            acc.z += v.z * w.z; acc.w += v.w * w.w;
        }
    }
    size_t o = ((((size_t)b * H2 + i) * W2) + j) * C4 + c0;
    float vv[4] = {acc.x, acc.y, acc.z, acc.w};
    bf16 hb[4], lb[4];
    #pragma unroll
    for (int q = 0; q < 4; q++) {
        hb[q] = __float2bfloat16(vv[q]);
        lb[q] = __float2bfloat16(vv[q] - __bfloat162float(hb[q]));
    }
    *(uint2*)(g_a_hi + o) = *(uint2*)hb;
    *(uint2*)(g_a_lo + o) = *(uint2*)lb;
}

// ---------------------------------------------------------------------------
// mma.sync GEMM conv. CTA: M=128(j) x N=256(all oc), 512 thr, warp grid 4x4.
// 3-stage cp.async pipeline, 1 sync per chunk. Split: Ah*Bh + Al*Bh + Ah*Bl.
// ---------------------------------------------------------------------------
template<int TAPS>
__device__ __forceinline__ void load_stage(uint32_t sb, int slot,
                                           const bf16* __restrict__ ah,
                                           const bf16* __restrict__ al,
                                           const bf16* __restrict__ wh,
                                           const bf16* __restrict__ wl,
                                           int b, int i, int chunk, int t) {
    const int tap = (TAPS == 9) ? (chunk >> 3) : 0;
    const int ic0 = (TAPS == 9) ? ((chunk & 7) * 32) : (chunk * 32);
    const int KTOT = TAPS * 256;
    uint32_t st = sb + slot * STAGE_B;

    // A: 128 rows x 64B, hi+lo (1 unit each per thread)
    {
        int row = t >> 2, q = t & 3;
        int ii = (TAPS == 9) ? (i + tap / 3 - 1) : i;
        int jj = (TAPS == 9) ? (row + tap % 3 - 1) : row;
        bool ok = ((unsigned)ii < (unsigned)H2) && ((unsigned)jj < (unsigned)W2);
        if (!ok) { ii = 0; jj = 0; }
        size_t goff = (((size_t)b * H2 + ii) * W2 + jj) * (size_t)C4 + ic0 + q * 8;
        uint32_t dA = st + row * ROWP + q * 16;
        cpa16(dA + OFF_AH, ah + goff, ok);
        cpa16(dA + OFF_AL, al + goff, ok);
    }
    // B: 256 rows x 64B, hi+lo (2 units each per thread)
    #pragma unroll
    for (int rep = 0; rep < 2; rep++) {
        int slotb = t + rep * 512;
        int row = slotb >> 2, q = slotb & 3;
        size_t w = (size_t)row * KTOT + tap * 256 + ic0 + q * 8;
        uint32_t dB = st + row * ROWP + q * 16;
        cpa16(dB + OFF_BH, wh + w, true);
        cpa16(dB + OFF_BL, wl + w, true);
    }
}

template<int TAPS, bool GELU_OUT>
__global__ void __launch_bounds__(512, 1)
gemm_mma_kernel(const float* __restrict__ bias) {
    extern __shared__ char smem[];
    uint32_t sb = smem_to_u32(smem);
    const int t = threadIdx.x;
    const int lane = t & 31, wid = t >> 5;
    const int mw = wid & 3, nw = wid >> 2;   // 4(m) x 4(n)
    const int bi = blockIdx.x;
    const int b = bi >> 7, i = bi & 127;

    const bf16* ah = (TAPS == 9) ? g_b_hi : g_a_hi;
    const bf16* al = (TAPS == 9) ? g_b_lo : g_a_lo;
    const bf16* wh = (TAPS == 9) ? g_cv_hi : g_pw_hi;
    const bf16* wl = (TAPS == 9) ? g_cv_lo : g_pw_lo;

    float acc[2][8][4];
    #pragma unroll
    for (int tm = 0; tm < 2; tm++)
        #pragma unroll
        for (int tn = 0; tn < 8; tn++)
            #pragma unroll
            for (int q = 0; q < 4; q++) acc[tm][tn][q] = 0.0f;

    uint32_t aoff[2], boff[4];
    #pragma unroll
    for (int tm = 0; tm < 2; tm++)
        aoff[tm] = (mw * 32 + tm * 16 + (lane & 15)) * ROWP + (lane >> 4) * 16;
    #pragma unroll
    for (int g = 0; g < 4; g++)
        boff[g] = (nw * 64 + g * 16 + ((lane >> 4) & 1) * 8 + (lane & 7)) * ROWP
                + ((lane >> 3) & 1) * 16;

    const int NC = TAPS * 8;

    load_stage<TAPS>(sb, 0, ah, al, wh, wl, b, i, 0, t);
    cpa_commit();
    load_stage<TAPS>(sb, 1, ah, al, wh, wl, b, i, 1, t);
    cpa_commit();

    int slot = 0;
    for (int c = 0; c < NC; c++) {
        cpa_wait<1>();
        __syncthreads();

        uint32_t st = sb + slot * STAGE_B;
        uint32_t Ahp = st + OFF_AH, Alp = st + OFF_AL;
        uint32_t Bhp = st + OFF_BH, Blp = st + OFF_BL;

        #pragma unroll
        for (int kh = 0; kh < 2; kh++) {
            uint32_t a_hi[2][4], a_lo[2][4], bfrag[4][4];
            #pragma unroll
            for (int tm = 0; tm < 2; tm++) ldsm4(a_hi[tm], Ahp + aoff[tm] + kh * 32);
            #pragma unroll
            for (int g = 0; g < 4; g++) ldsm4(bfrag[g], Bhp + boff[g] + kh * 32);
            // Ah * Bh
            #pragma unroll
            for (int tm = 0; tm < 2; tm++)
                #pragma unroll
                for (int g = 0; g < 4; g++) {
                    mma16816(acc[tm][2 * g],     a_hi[tm], bfrag[g][0], bfrag[g][1]);
                    mma16816(acc[tm][2 * g + 1], a_hi[tm], bfrag[g][2], bfrag[g][3]);
                }
            // Al * Bh (reuse bfrag)
            #pragma unroll
            for (int tm = 0; tm < 2; tm++) ldsm4(a_lo[tm], Alp + aoff[tm] + kh * 32);
            #pragma unroll
            for (int tm = 0; tm < 2; tm++)
                #pragma unroll
                for (int g = 0; g < 4; g++) {
                    mma16816(acc[tm][2 * g],     a_lo[tm], bfrag[g][0], bfrag[g][1]);
                    mma16816(acc[tm][2 * g + 1], a_lo[tm], bfrag[g][2], bfrag[g][3]);
                }
            // Ah * Bl
            #pragma unroll
            for (int g = 0; g < 4; g++) ldsm4(bfrag[g], Blp + boff[g] + kh * 32);
            #pragma unroll
            for (int tm = 0; tm < 2; tm++)
                #pragma unroll
                for (int g = 0; g < 4; g++) {
                    mma16816(acc[tm][2 * g],     a_hi[tm], bfrag[g][0], bfrag[g][1]);
                    mma16816(acc[tm][2 * g + 1], a_hi[tm], bfrag[g][2], bfrag[g][3]);
                }
        }

        // prefetch chunk c+2 into the third slot (safe: slot != c%3, (c+1)%3)
        if (c + 2 < NC)
            load_stage<TAPS>(sb, (slot + 2) % NSTAGE, ah, al, wh, wl, b, i, c + 2, t);
        cpa_commit();
        slot = (slot + 1) % NSTAGE;
    }

    // Epilogue from register accumulators
    const int r = lane >> 2, cpair = (lane & 3) * 2;
    #pragma unroll
    for (int tm = 0; tm < 2; tm++) {
        #pragma unroll
        for (int tn = 0; tn < 8; tn++) {
            int oc = nw * 64 + tn * 8 + cpair;
            float bz0 = __ldg(bias + oc), bz1 = __ldg(bias + oc + 1);
            int j0 = mw * 32 + tm * 16 + r;
            #pragma unroll
            for (int half = 0; half < 2; half++) {
                int j = j0 + half * 8;
                float v0 = acc[tm][tn][half * 2 + 0] + bz0;
                float v1 = acc[tm][tn][half * 2 + 1] + bz1;
                size_t off = ((((size_t)b * H2 + i) * W2) + j) * C4 + oc;
                if (GELU_OUT) {
                    *(float2*)(g_t0 + off) = make_float2(gelu_exact(v0), gelu_exact(v1));
                } else {
                    bf16 h0 = __float2bfloat16(v0);
                    bf16 h1 = __float2bfloat16(v1);
                    bf16 l0 = __float2bfloat16(v0 - __bfloat162float(h0));
                    bf16 l1 = __float2bfloat16(v1 - __bfloat162float(h1));
                    bf16 hp[2] = {h0, h1};
                    bf16 lp[2] = {l0, l1};
                    *(uint32_t*)(g_b_hi + off) = *(uint32_t*)hp;
                    *(uint32_t*)(g_b_lo + off) = *(uint32_t*)lp;
                }
            }
        }
    }
}

// ---------------------------------------------------------------------------
// IDWT: t0 (fp32 NHWC) -> out (NCHW)
// ---------------------------------------------------------------------------
__global__ void idwt_kernel(float* __restrict__ out) {
    __shared__ float4 s[16][17];
    int b = blockIdx.z;
    int h2 = blockIdx.y;
    int ctile = blockIdx.x >> 3;
    int wtile = blockIdx.x & 7;
    int tx = threadIdx.x, ty = threadIdx.y;

    int c = ctile * 16 + tx;
    int w2 = wtile * 16 + ty;
    s[ty][tx] = *(const float4*)(g_t0 + ((((size_t)b * H2 + w2) * W2) + h2) * C4 + 4 * c);
    __syncthreads();

    float4 v = s[tx][ty];
    int c2 = ctile * 16 + ty;
    int w2b = wtile * 16 + tx;
    float ll = v.x, ch = v.y, cv = v.z, cd = v.w;
    float a  = (ll + ch + cv + cd) * 0.5f;
    float bq = (ll + ch - cv - cd) * 0.5f;
    float cq = (ll - ch + cv - cd) * 0.5f;
    float dq = (ll - ch - cv + cd) * 0.5f;
    float* o = out + (((size_t)(b * CC + c2) * 256) + 2 * h2) * 256 + 2 * w2b;
    *(float2*)o         = make_float2(a, bq);
    *(float2*)(o + 256) = make_float2(cq, dq);
}

// ---------------------------------------------------------------------------
extern "C" void kernel_launch(void* const* d_in, const int* in_sizes, int n_in,
                              void* d_out, int out_size) {
    const float* x    = (const float*)d_in[0];
    const float* dw_w = (const float*)d_in[1];
    const float* dw_b = (const float*)d_in[2];
    const float* pw_w = (const float*)d_in[3];
    const float* pw_b = (const float*)d_in[4];
    const float* cv_w = (const float*)d_in[5];
    const float* cv_b = (const float*)d_in[6];
    float* out = (float*)d_out;

    cudaFuncSetAttribute(gemm_mma_kernel<1, false>,
                         cudaFuncAttributeMaxDynamicSharedMemorySize, SMEM_DYN);
    cudaFuncSetAttribute(gemm_mma_kernel<9, true>,
                         cudaFuncAttributeMaxDynamicSharedMemorySize, SMEM_DYN);

    prep_kernel<<<512, 256>>>(dw_w, pw_w, cv_w);
    dwt_kernel<<<dim3(32, 128, BB), dim3(16, 16)>>>(x);
    dw_kernel<<<dim3(32, 128, BB), dim3(64, 4)>>>(dw_b);
    gemm_mma_kernel<1, false><<<1024, 512, SMEM_DYN>>>(pw_b);
    gemm_mma_kernel<9, true><<<1024, 512, SMEM_DYN>>>(cv_b);
    idwt_kernel<<<dim3(32, 128, BB), dim3(16, 16)>>>(out);
}